// round 16
// baseline (speedup 1.0000x reference)
#include <cuda_runtime.h>
#include <cstdint>

// out[t][l][d]: l==0 -> inputs[t][d], else memory[l][d]
// T=2048, L=64, D=1024 fp32. Pure store-bandwidth kernel (512 MiB writes).
//
// Bulk-store granularity test: STG paths emit 512 B/warp requests; here each
// block stages U=4 contiguous output rows (16 KiB) in smem and issues ONE
// cp.async.bulk shared->global store (UBLKCP) -> 16 KiB fully-contiguous
// write requests for better DRAM row-burst scheduling.
// smem 16 KiB x occ 8 = 128 KiB/SM (fits 228 KiB). Champion fallback: R10.

static constexpr int T = 2048;
static constexpr int L = 64;
static constexpr int D4 = 1024 / 4;            // 256 float4 per row
static constexpr int ROWS = T * L;             // 131072
static constexpr int U = 4;                    // rows per block (contiguous in out)
static constexpr int TILE_BYTES = U * D4 * 16; // 16384

__global__ __launch_bounds__(256, 8)
void sliding_window_memory_kernel(const float4* __restrict__ in,
                                  const float4* __restrict__ mem,
                                  float4* __restrict__ out)
{
    __shared__ alignas(128) float4 buf[U * D4];

    const int tid = threadIdx.x;
    const int row0 = blockIdx.x * U;

    // batched loads (champion pattern), stage into smem
    float4 v[U];
#pragma unroll
    for (int u = 0; u < U; ++u) {
        const int row = row0 + u;
        const int l = row & (L - 1);
        const int t = row >> 6;
        const float4* __restrict__ s =
            (l == 0) ? (in + t * D4 + tid) : (mem + l * D4 + tid);
        v[u] = __ldg(s);
    }
#pragma unroll
    for (int u = 0; u < U; ++u)
        buf[u * D4 + tid] = v[u];

    __syncthreads();
    // order generic-proxy smem writes before async-proxy (bulk) reads
    asm volatile("fence.proxy.async.shared::cta;" ::: "memory");

    if (tid == 0) {
        unsigned int saddr;
        asm("{ .reg .u64 t; cvta.to.shared.u64 t, %1; cvt.u32.u64 %0, t; }"
            : "=r"(saddr) : "l"(buf));
        const float4* gdst = out + (long)row0 * D4;
        asm volatile(
            "cp.async.bulk.global.shared::cta.bulk_group [%0], [%1], %2;"
            :: "l"(gdst), "r"(saddr), "r"((int)TILE_BYTES) : "memory");
        asm volatile("cp.async.bulk.commit_group;" ::: "memory");
        asm volatile("cp.async.bulk.wait_group 0;" ::: "memory");
    }
    // all threads must outlive the bulk read of smem
    __syncthreads();
}

extern "C" void kernel_launch(void* const* d_in, const int* in_sizes, int n_in,
                              void* d_out, int out_size)
{
    const float4* in  = (const float4*)d_in[0];   // inputs [T, D] fp32
    const float4* mem = (const float4*)d_in[1];   // memory [L, D] fp32
    float4* out = (float4*)d_out;                 // [T, L, D] fp32

    const int threads = 256;
    const int blocks = ROWS / U;                  // 32768
    sliding_window_memory_kernel<<<blocks, threads>>>(in, mem, out);
}

// round 17
// speedup vs baseline: 1.0877x; 1.0877x over previous
#include <cuda_runtime.h>

// out[t][l][d]: l==0 -> inputs[t][d], else memory[l][d]
// T=2048, L=64, D=1024 fp32. Pure store-bandwidth kernel (512 MiB compulsory
// writes). FINAL champion configuration (R10, best of 16 rounds / 10 A/B'd
// mechanisms):
//   - block = 256 threads = one float4-row of D; U=2 rows per block with
//     batched loads then batched stores (U-sweep: 8/4/2/1 ->
//     75.0/74.2/73.9/74.5 us; interleaved 74.6; 512-thr 74.6)
//   - __ldg loads (input rows DRAM-once; 258 KiB tail L2-resident)
//   - __stcs evict-first streaming stores (vs write-back: 73.9 vs 82.7)
//   - falsified alternatives: 256-bit v8 (80.5), tail-dedup transpose (76.3),
//     persistent grid (87.9), wave balancing (75.5), bulk UBLKCP (81.0)
// ~7.3 TB/s effective = ~91% of HBM3e spec; all SM pipes <10% busy ->
// verified DRAM write-drain roofline.

static constexpr int T = 2048;
static constexpr int L = 64;
static constexpr int D4 = 1024 / 4;            // 256 float4 per row
static constexpr int ROWS = T * L;             // 131072
static constexpr int U = 2;                    // rows per block

__global__ __launch_bounds__(256, 8)
void sliding_window_memory_kernel(const float4* __restrict__ in,
                                  const float4* __restrict__ mem,
                                  float4* __restrict__ out)
{
    const int tid = threadIdx.x;
    const int row0 = blockIdx.x * U;

    float4* __restrict__ o = out + (long)row0 * D4 + tid;

    float4 v[U];
#pragma unroll
    for (int u = 0; u < U; ++u) {
        const int row = row0 + u;
        const int l = row & (L - 1);
        const int t = row >> 6;
        const float4* __restrict__ s =
            (l == 0) ? (in + t * D4 + tid) : (mem + l * D4 + tid);
        v[u] = __ldg(s);                  // in: DRAM once; mem tail: L2-resident
    }
#pragma unroll
    for (int u = 0; u < U; ++u) {
        __stcs(o + u * D4, v[u]);         // streaming store
    }
}

extern "C" void kernel_launch(void* const* d_in, const int* in_sizes, int n_in,
                              void* d_out, int out_size)
{
    const float4* in  = (const float4*)d_in[0];   // inputs [T, D] fp32
    const float4* mem = (const float4*)d_in[1];   // memory [L, D] fp32
    float4* out = (float4*)d_out;                 // [T, L, D] fp32

    const int threads = 256;
    const int blocks = ROWS / U;                  // 65536
    sliding_window_memory_kernel<<<blocks, threads>>>(in, mem, out);
}